// round 2
// baseline (speedup 1.0000x reference)
#include <cuda_runtime.h>
#include <math.h>

// Problem dims
#define NB   128     // tokens
#define DD   2560    // D
#define DN   5120    // DIN
#define SS   16
#define RR   160
#define PJ   192     // R + 2S

// ---------------- scratch (device globals: allocation-free) ----------------
__device__ float g_xs  [NB * DN];   // x @ ssm_proj (split-K accumulated)
__device__ float g_res [NB * DN];   // x @ mlp_proj
__device__ float g_u   [NB * DN];   // silu(conv_out)
__device__ float g_proj[NB * PJ];   // u @ x_proj_w
__device__ float g_g   [NB * DN];   // y * res

// ---------------- f32x2 helpers ----------------
__device__ __forceinline__ void fma2(unsigned long long& acc,
                                     unsigned long long a,
                                     unsigned long long b) {
    asm volatile("fma.rn.f32x2 %0, %1, %2, %0;" : "+l"(acc) : "l"(a), "l"(b));
}
__device__ __forceinline__ unsigned long long pack2(float lo, float hi) {
    unsigned long long r;
    asm("mov.b64 %0, {%1, %2};" : "=l"(r)
        : "r"(__float_as_uint(lo)), "r"(__float_as_uint(hi)));
    return r;
}
__device__ __forceinline__ void unpack2(unsigned long long v, float& lo, float& hi) {
    unsigned int a, b;
    asm("mov.b64 {%0, %1}, %2;" : "=r"(a), "=r"(b) : "l"(v));
    lo = __uint_as_float(a);
    hi = __uint_as_float(b);
}

// ---------------- zero scratch + output ----------------
__global__ void zero_all(float* __restrict__ out) {
    int i = blockIdx.x * blockDim.x + threadIdx.x;  // grid covers NB*DN
    if (i < NB * DN) { g_xs[i] = 0.0f; g_res[i] = 0.0f; }
    if (i < NB * PJ) g_proj[i] = 0.0f;
    if (i < NB * DD) out[i] = 0.0f;
}

// ---------------- generic split-K SGEMM, C += A@B via atomics ----------------
// A: [128, K] row-major (lda), B: [K, N] row-major (ldb = N), C: [128, N].
// grid = (N/64, KSPLIT), block = 256. BM=128, BN=64, BK=16.
// Thread (ty,tx) of 16x16 computes rows ty*8..+7 (as 4 row-pairs), cols tx*4..+3.
__global__ __launch_bounds__(256, 3)
void sgemm_atomic(const float* __restrict__ A, const float* __restrict__ B,
                  float* __restrict__ C, int K, int N, int lda, int kslice) {
    __shared__ float As[16][128];
    __shared__ float Bs[16][64];

    const int n0 = blockIdx.x * 64;
    int k0 = blockIdx.y * kslice;
    int kend = k0 + kslice;
    if (kend > K) kend = K;

    const int t  = threadIdx.x;
    const int ty = t >> 4;
    const int tx = t & 15;

    // A-tile loader mapping: row an, k-segment aseg (8 floats each)
    const int an   = t >> 1;
    const int aseg = t & 1;
    // B-tile loader mapping: row bk, 4 cols at bj
    const int bk = t >> 4;
    const int bj = (t & 15) << 2;

    unsigned long long acc[4][4];
#pragma unroll
    for (int i = 0; i < 4; i++)
#pragma unroll
        for (int j = 0; j < 4; j++) acc[i][j] = 0ull;

    for (; k0 < kend; k0 += 16) {
        const float4 av0 = *reinterpret_cast<const float4*>(A + an * lda + k0 + aseg * 8);
        const float4 av1 = *reinterpret_cast<const float4*>(A + an * lda + k0 + aseg * 8 + 4);
        const float4 bv  = *reinterpret_cast<const float4*>(B + (k0 + bk) * N + n0 + bj);

        As[aseg * 8 + 0][an] = av0.x;
        As[aseg * 8 + 1][an] = av0.y;
        As[aseg * 8 + 2][an] = av0.z;
        As[aseg * 8 + 3][an] = av0.w;
        As[aseg * 8 + 4][an] = av1.x;
        As[aseg * 8 + 5][an] = av1.y;
        As[aseg * 8 + 6][an] = av1.z;
        As[aseg * 8 + 7][an] = av1.w;
        *reinterpret_cast<float4*>(&Bs[bk][bj]) = bv;
        __syncthreads();

#pragma unroll
        for (int kk = 0; kk < 16; kk++) {
            unsigned long long a[4];
#pragma unroll
            for (int i = 0; i < 4; i++)
                a[i] = *reinterpret_cast<const unsigned long long*>(&As[kk][ty * 8 + 2 * i]);
            const float4 b4 = *reinterpret_cast<const float4*>(&Bs[kk][tx * 4]);
            unsigned long long b[4];
            b[0] = pack2(b4.x, b4.x);
            b[1] = pack2(b4.y, b4.y);
            b[2] = pack2(b4.z, b4.z);
            b[3] = pack2(b4.w, b4.w);
#pragma unroll
            for (int i = 0; i < 4; i++)
#pragma unroll
                for (int j = 0; j < 4; j++) fma2(acc[i][j], a[i], b[j]);
        }
        __syncthreads();
    }

#pragma unroll
    for (int i = 0; i < 4; i++) {
        const int r0 = ty * 8 + 2 * i;
#pragma unroll
        for (int j = 0; j < 4; j++) {
            float lo, hi;
            unpack2(acc[i][j], lo, hi);
            const int c = n0 + tx * 4 + j;
            atomicAdd(&C[r0 * N + c], lo);
            atomicAdd(&C[(r0 + 1) * N + c], hi);
        }
    }
}

// ---------------- conv (depthwise 4-tap on last state) + SiLU ----------------
// states = (conv_state1, conv_state2, conv_state3, xs); conv_state0 is unused.
__global__ void conv_silu(const float* __restrict__ cs1, const float* __restrict__ cs2,
                          const float* __restrict__ cs3, const float* __restrict__ cw,
                          const float* __restrict__ cb) {
    int i = blockIdx.x * blockDim.x + threadIdx.x;
    if (i >= NB * DN) return;
    int d = i % DN;
    float v = cb[d]
            + cw[0 * DN + d] * cs1[i]
            + cw[1 * DN + d] * cs2[i]
            + cw[2 * DN + d] * cs3[i]
            + cw[3 * DN + d] * g_xs[i];
    g_u[i] = v / (1.0f + expf(-v));   // silu
}

// ---------------- fused dt-GEMM + softplus + SSM scan + gate ----------------
// grid = (DN/256, NB/8), block = 256. Each thread owns one d, 8 tokens.
__global__ __launch_bounds__(256)
void ssm_kernel(const float* __restrict__ dt_w,    // [160, 5120]
                const float* __restrict__ dt_b,    // [5120]
                const float* __restrict__ A_log,   // [5120, 16]
                const float* __restrict__ state,   // [128, 5120, 16]
                const float* __restrict__ D_param) // [5120]
{
    const int d  = blockIdx.x * 256 + threadIdx.x;
    const int nb = blockIdx.y * 8;

    __shared__ float pj[8][PJ];
    for (int i = threadIdx.x; i < 8 * PJ; i += 256)
        pj[i / PJ][i % PJ] = g_proj[(nb + i / PJ) * PJ + (i % PJ)];
    __syncthreads();

    // dt_pre[i] = bias + proj[n, :160] @ dt_proj_w[:, d]
    float dtp[8];
    const float bias = dt_b[d];
#pragma unroll
    for (int i = 0; i < 8; i++) dtp[i] = bias;
#pragma unroll 4
    for (int r = 0; r < RR; r++) {
        const float w = dt_w[r * DN + d];
#pragma unroll
        for (int i = 0; i < 8; i++) dtp[i] += pj[i][r] * w;
    }

    float Aa[SS];
#pragma unroll
    for (int s = 0; s < SS; s++) Aa[s] = -expf(A_log[d * SS + s]);
    const float Dv = D_param[d];

#pragma unroll
    for (int i = 0; i < 8; i++) {
        const int n = nb + i;
        const float x  = dtp[i];
        const float dt = (x > 20.0f) ? x : log1pf(expf(x));  // softplus
        const float uv = g_u[n * DN + d];
        const float rv = g_res[n * DN + d];
        const float4* st = reinterpret_cast<const float4*>(state + ((long)n * DN + d) * SS);
        float y = 0.0f;
#pragma unroll
        for (int q = 0; q < 4; q++) {
            const float4 sv = st[q];
            {   const int s = q * 4 + 0;
                const float h = expf(dt * Aa[s]) * sv.x + dt * pj[i][RR + s] * uv;
                y += h * pj[i][RR + SS + s]; }
            {   const int s = q * 4 + 1;
                const float h = expf(dt * Aa[s]) * sv.y + dt * pj[i][RR + s] * uv;
                y += h * pj[i][RR + SS + s]; }
            {   const int s = q * 4 + 2;
                const float h = expf(dt * Aa[s]) * sv.z + dt * pj[i][RR + s] * uv;
                y += h * pj[i][RR + SS + s]; }
            {   const int s = q * 4 + 3;
                const float h = expf(dt * Aa[s]) * sv.w + dt * pj[i][RR + s] * uv;
                y += h * pj[i][RR + SS + s]; }
        }
        y += Dv * uv;
        g_g[n * DN + d] = y * rv;
    }
}

// ---------------- launcher ----------------
extern "C" void kernel_launch(void* const* d_in, const int* in_sizes, int n_in,
                              void* d_out, int out_size) {
    const float* x        = (const float*)d_in[0];
    // d_in[1] = conv_state0 (unused by the reference)
    const float* cs1      = (const float*)d_in[2];
    const float* cs2      = (const float*)d_in[3];
    const float* cs3      = (const float*)d_in[4];
    const float* state    = (const float*)d_in[5];
    const float* ssm_proj = (const float*)d_in[6];
    const float* mlp_proj = (const float*)d_in[7];
    const float* down_prj = (const float*)d_in[8];
    const float* conv_w   = (const float*)d_in[9];
    const float* conv_b   = (const float*)d_in[10];
    const float* x_proj_w = (const float*)d_in[11];
    const float* dt_w     = (const float*)d_in[12];
    const float* dt_b     = (const float*)d_in[13];
    const float* A_log    = (const float*)d_in[14];
    const float* Dp       = (const float*)d_in[15];
    float* out = (float*)d_out;

    void *p_xs, *p_res, *p_u, *p_proj, *p_g;
    cudaGetSymbolAddress(&p_xs,   g_xs);
    cudaGetSymbolAddress(&p_res,  g_res);
    cudaGetSymbolAddress(&p_u,    g_u);
    cudaGetSymbolAddress(&p_proj, g_proj);
    cudaGetSymbolAddress(&p_g,    g_g);

    // 0) zero accumulators + output
    zero_all<<<(NB * DN + 255) / 256, 256>>>(out);

    // 1) xs = x @ ssm_proj   (K=2560, N=5120, split-K 4)
    sgemm_atomic<<<dim3(DN / 64, 4), 256>>>(x, ssm_proj, (float*)p_xs,
                                            DD, DN, DD, DD / 4);
    // 2) res = x @ mlp_proj
    sgemm_atomic<<<dim3(DN / 64, 4), 256>>>(x, mlp_proj, (float*)p_res,
                                            DD, DN, DD, DD / 4);
    // 3) u = silu(conv_bias + w0*cs1 + w1*cs2 + w2*cs3 + w3*xs)
    conv_silu<<<(NB * DN + 255) / 256, 256>>>(cs1, cs2, cs3, conv_w, conv_b);

    // 4) proj = u @ x_proj_w  (K=5120, N=192, split-K 40)
    sgemm_atomic<<<dim3(PJ / 64, 40), 256>>>((const float*)p_u, x_proj_w,
                                             (float*)p_proj, DN, PJ, DN, 128);

    // 5) dt GEMM + softplus + SSM scan + D*u + gate by res -> g_g
    ssm_kernel<<<dim3(DN / 256, NB / 8), 256>>>(dt_w, dt_b, A_log, state, Dp);

    // 6) out = g_g @ down_proj  (K=5120, N=2560, split-K 8)
    sgemm_atomic<<<dim3(DD / 64, 8), 256>>>((const float*)p_g, down_prj, out,
                                            DN, DD, DN, DN / 8);
}

// round 4
// speedup vs baseline: 1.6730x; 1.6730x over previous
#include <cuda_runtime.h>
#include <cuda_bf16.h>
#include <math.h>

// Problem dims
#define NB   128     // tokens
#define DD   2560    // D
#define DN   5120    // DIN
#define SS   16
#define RR   160
#define PJ   192     // R + 2S
#define CH_K 32      // K elements per chunk

// ---------------- scratch (device globals: allocation-free) ----------------
__device__ float g_res [NB * DN];   // x @ mlp_proj
__device__ float g_u   [NB * DN];   // silu(conv_out)
__device__ float g_proj[NB * PJ];   // u @ x_proj_w
__device__ float g_g   [NB * DN];   // y * res
__device__ __nv_bfloat16 g_xhi[NB * DD];
__device__ __nv_bfloat16 g_xlo[NB * DD];
__device__ __nv_bfloat16 g_ghi[NB * DN];
__device__ __nv_bfloat16 g_glo[NB * DN];

// ---------------- f32x2 helpers (for the small fp32 proj GEMM) -------------
__device__ __forceinline__ void fma2(unsigned long long& acc,
                                     unsigned long long a,
                                     unsigned long long b) {
    asm volatile("fma.rn.f32x2 %0, %1, %2, %0;" : "+l"(acc) : "l"(a), "l"(b));
}
__device__ __forceinline__ unsigned long long pack2(float lo, float hi) {
    unsigned long long r;
    asm("mov.b64 %0, {%1, %2};" : "=l"(r)
        : "r"(__float_as_uint(lo)), "r"(__float_as_uint(hi)));
    return r;
}
__device__ __forceinline__ void unpack2(unsigned long long v, float& lo, float& hi) {
    unsigned int a, b;
    asm("mov.b64 {%0, %1}, %2;" : "=r"(a), "=r"(b) : "l"(v));
    lo = __uint_as_float(a);
    hi = __uint_as_float(b);
}

__device__ __forceinline__ unsigned smem_u32(const void* p) {
    unsigned a;
    asm("{ .reg .u64 t; cvta.to.shared.u64 t, %1; cvt.u32.u64 %0, t; }"
        : "=r"(a) : "l"(p));
    return a;
}

// ---------------- mma / ldmatrix primitives (sm_80+ PTX, no arch gates) ----
#define LDSM_X4(r0, r1, r2, r3, a)                                            \
    asm volatile("ldmatrix.sync.aligned.m8n8.x4.shared.b16 {%0,%1,%2,%3}, [%4];" \
        : "=r"(r0), "=r"(r1), "=r"(r2), "=r"(r3) : "r"(a))
#define LDSM_X4T(r0, r1, r2, r3, a)                                           \
    asm volatile("ldmatrix.sync.aligned.m8n8.x4.trans.shared.b16 {%0,%1,%2,%3}, [%4];" \
        : "=r"(r0), "=r"(r1), "=r"(r2), "=r"(r3) : "r"(a))
#define MMA_BF16(c, a, b0, b1)                                                \
    asm volatile("mma.sync.aligned.m16n8k16.row.col.f32.bf16.bf16.f32 "       \
        "{%0,%1,%2,%3}, {%4,%5,%6,%7}, {%8,%9}, {%0,%1,%2,%3};"               \
        : "+f"((c)[0]), "+f"((c)[1]), "+f"((c)[2]), "+f"((c)[3])              \
        : "r"((a)[0]), "r"((a)[1]), "r"((a)[2]), "r"((a)[3]),                 \
          "r"(b0), "r"(b1))

// SMEM layout (bytes, within dynamic smem)
// A tiles padded to 40 bf16/row (80B, 16B-aligned, conflict-free ldmatrix)
// B tiles padded to 72 bf16/row (144B)
#define A_PITCH 40
#define B_PITCH 72
#define SZ_A    (128 * A_PITCH * 2)      // 10240
#define SZ_B    (CH_K * B_PITCH * 2)     // 4608
#define OFF_AH(b) ((b) * SZ_A)
#define OFF_AL(b) (2 * SZ_A + (b) * SZ_A)
#define OFF_BH(b) (4 * SZ_A + (b) * SZ_B)
#define OFF_BL(b) (4 * SZ_A + 2 * SZ_B + (b) * SZ_B)
#define SMEM_DYN (4 * SZ_A + 4 * SZ_B)   // 59392

// ---------------- zero scratch + output ----------------
__global__ void zero_k(float* __restrict__ out) {
    int i = blockIdx.x * blockDim.x + threadIdx.x;
    if (i < NB * DD) out[i] = 0.0f;
    if (i < NB * PJ) g_proj[i] = 0.0f;
}

// ---------------- fp32 -> bf16 hi/lo split ----------------
__global__ void convert_split(const float* __restrict__ src,
                              __nv_bfloat16* __restrict__ hi,
                              __nv_bfloat16* __restrict__ lo, int n) {
    int i = blockIdx.x * blockDim.x + threadIdx.x;
    if (i >= n) return;
    float v = src[i];
    __nv_bfloat16 h = __float2bfloat16(v);
    hi[i] = h;
    lo[i] = __float2bfloat16(v - __bfloat162float(h));
}

// ---------------- HMMA 3-term bf16-split GEMM ----------------
// D[128, 64-tile] = A[128,K] @ W[K,N]; A pre-split hi/lo bf16 (row-major),
// W fp32 [K,N] split on the fly into SMEM.
// mode 0: grid.x=160; bx<80 -> W0 (ssm), epilogue conv+SiLU -> C0 (g_u)
//                     bx>=80 -> W1 (mlp), direct store -> C1 (g_res)
// mode 2: grid (Ntiles, 4) split-K, atomicAdd -> C0
__global__ __launch_bounds__(256)
void gemm_hmma(const __nv_bfloat16* __restrict__ Ahi,
               const __nv_bfloat16* __restrict__ Alo,
               int ldA, int kChunks,
               const float* __restrict__ W0, const float* __restrict__ W1,
               int ldW,
               float* __restrict__ C0, float* __restrict__ C1,
               int mode,
               const float* __restrict__ cs1, const float* __restrict__ cs2,
               const float* __restrict__ cs3, const float* __restrict__ cw,
               const float* __restrict__ cb) {
    extern __shared__ char sb[];
    const unsigned sm = smem_u32(sb);

    const int t    = threadIdx.x;
    const int lane = t & 31;
    const int wid  = t >> 5;
    const int wm   = wid & 3;    // warp m-block (4 x 32 rows)
    const int wn   = wid >> 2;   // warp n-block (2 x 32 cols)

    const float* W;
    float* C;
    int n0, emode;
    if (mode == 0) {
        int bx = blockIdx.x;
        if (bx < 80) { W = W0; C = C0; n0 = bx * 64; emode = 0; }
        else         { W = W1; C = C1; n0 = (bx - 80) * 64; emode = 1; }
    } else {
        W = W0; C = C0; n0 = blockIdx.x * 64; emode = 2;
    }
    const int ldC = ldW;
    const int kStart = blockIdx.y * kChunks * CH_K;

    // ---- per-thread load mappings ----
    // A: 512 16B-units per tile; thread handles units t and t+256.
    const int ar0 = t >> 1,           as0 = t & 1;          // unit t   (seg 0/1 of 4? no:)
    // unit u: row = u>>2, seg = u&3  (4 segs of 8 bf16 = 32 k)
    const int ua0r = t >> 2,          ua0s = t & 3;
    const int ua1r = (t + 256) >> 2,  ua1s = (t + 256) & 3;
    (void)ar0; (void)as0;
    // B: thread t: kk = t>>3, nseg = t&7 (8 fp32 each)
    const int bkk = t >> 3, bns = (t & 7) * 8;

    float acc[2][4][4];
#pragma unroll
    for (int i = 0; i < 2; i++)
#pragma unroll
        for (int j = 0; j < 4; j++)
#pragma unroll
            for (int q = 0; q < 4; q++) acc[i][j][q] = 0.0f;

    uint4 pAh[2], pAl[2];
    float4 pB[2];

    // prefetch chunk 0
    {
        const int kk0 = kStart;
        pAh[0] = *reinterpret_cast<const uint4*>(Ahi + (size_t)ua0r * ldA + kk0 + ua0s * 8);
        pAl[0] = *reinterpret_cast<const uint4*>(Alo + (size_t)ua0r * ldA + kk0 + ua0s * 8);
        pAh[1] = *reinterpret_cast<const uint4*>(Ahi + (size_t)ua1r * ldA + kk0 + ua1s * 8);
        pAl[1] = *reinterpret_cast<const uint4*>(Alo + (size_t)ua1r * ldA + kk0 + ua1s * 8);
        const float* wp = W + (size_t)(kk0 + bkk) * ldW + n0 + bns;
        pB[0] = *reinterpret_cast<const float4*>(wp);
        pB[1] = *reinterpret_cast<const float4*>(wp + 4);
    }

    int buf = 0;
    for (int c = 0; c < kChunks; c++) {
        // ---- store staged regs into SMEM buf ----
        {
            char* aH = sb + OFF_AH(buf);
            char* aL = sb + OFF_AL(buf);
            *reinterpret_cast<uint4*>(aH + (ua0r * A_PITCH + ua0s * 8) * 2) = pAh[0];
            *reinterpret_cast<uint4*>(aL + (ua0r * A_PITCH + ua0s * 8) * 2) = pAl[0];
            *reinterpret_cast<uint4*>(aH + (ua1r * A_PITCH + ua1s * 8) * 2) = pAh[1];
            *reinterpret_cast<uint4*>(aL + (ua1r * A_PITCH + ua1s * 8) * 2) = pAl[1];

            // split B fp32 -> hi/lo bf16 (8 elems)
            float v[8] = {pB[0].x, pB[0].y, pB[0].z, pB[0].w,
                          pB[1].x, pB[1].y, pB[1].z, pB[1].w};
            unsigned short hs[8], ls[8];
#pragma unroll
            for (int q = 0; q < 8; q++) {
                __nv_bfloat16 h = __float2bfloat16(v[q]);
                hs[q] = __bfloat16_as_ushort(h);
                ls[q] = __bfloat16_as_ushort(
                    __float2bfloat16(v[q] - __bfloat162float(h)));
            }
            uint4 hv, lv;
            hv.x = hs[0] | ((unsigned)hs[1] << 16);
            hv.y = hs[2] | ((unsigned)hs[3] << 16);
            hv.z = hs[4] | ((unsigned)hs[5] << 16);
            hv.w = hs[6] | ((unsigned)hs[7] << 16);
            lv.x = ls[0] | ((unsigned)ls[1] << 16);
            lv.y = ls[2] | ((unsigned)ls[3] << 16);
            lv.z = ls[4] | ((unsigned)ls[5] << 16);
            lv.w = ls[6] | ((unsigned)ls[7] << 16);
            *reinterpret_cast<uint4*>(sb + OFF_BH(buf) + (bkk * B_PITCH + bns) * 2) = hv;
            *reinterpret_cast<uint4*>(sb + OFF_BL(buf) + (bkk * B_PITCH + bns) * 2) = lv;
        }
        __syncthreads();

        // ---- prefetch next chunk ----
        if (c + 1 < kChunks) {
            const int kk0 = kStart + (c + 1) * CH_K;
            pAh[0] = *reinterpret_cast<const uint4*>(Ahi + (size_t)ua0r * ldA + kk0 + ua0s * 8);
            pAl[0] = *reinterpret_cast<const uint4*>(Alo + (size_t)ua0r * ldA + kk0 + ua0s * 8);
            pAh[1] = *reinterpret_cast<const uint4*>(Ahi + (size_t)ua1r * ldA + kk0 + ua1s * 8);
            pAl[1] = *reinterpret_cast<const uint4*>(Alo + (size_t)ua1r * ldA + kk0 + ua1s * 8);
            const float* wp = W + (size_t)(kk0 + bkk) * ldW + n0 + bns;
            pB[0] = *reinterpret_cast<const float4*>(wp);
            pB[1] = *reinterpret_cast<const float4*>(wp + 4);
        }

        // ---- compute from SMEM buf ----
        const unsigned aH = sm + OFF_AH(buf);
        const unsigned aL = sm + OFF_AL(buf);
        const unsigned bH = sm + OFF_BH(buf);
        const unsigned bL = sm + OFF_BL(buf);
#pragma unroll
        for (int ks = 0; ks < 2; ks++) {
            const int kof = ks * 16;
            unsigned ah[2][4], al[2][4], bh[2][4], bl[2][4];
            const int arow = wm * 32 + (lane & 15);
            const int acol = kof + (lane >> 4) * 8;
#pragma unroll
            for (int mt = 0; mt < 2; mt++) {
                unsigned off = ((arow + mt * 16) * A_PITCH + acol) * 2;
                LDSM_X4(ah[mt][0], ah[mt][1], ah[mt][2], ah[mt][3], aH + off);
                LDSM_X4(al[mt][0], al[mt][1], al[mt][2], al[mt][3], aL + off);
            }
            const int brow = kof + (lane & 15);
#pragma unroll
            for (int np = 0; np < 2; np++) {
                unsigned off = (brow * B_PITCH
                                + wn * 32 + np * 16 + (lane >> 4) * 8) * 2;
                LDSM_X4T(bh[np][0], bh[np][1], bh[np][2], bh[np][3], bH + off);
                LDSM_X4T(bl[np][0], bl[np][1], bl[np][2], bl[np][3], bL + off);
            }
#pragma unroll
            for (int mt = 0; mt < 2; mt++)
#pragma unroll
                for (int nt = 0; nt < 4; nt++) {
                    const int np = nt >> 1, sub = (nt & 1) * 2;
                    MMA_BF16(acc[mt][nt], ah[mt], bh[np][sub], bh[np][sub + 1]);
                    MMA_BF16(acc[mt][nt], al[mt], bh[np][sub], bh[np][sub + 1]);
                    MMA_BF16(acc[mt][nt], ah[mt], bl[np][sub], bl[np][sub + 1]);
                }
        }
        __syncthreads();
        buf ^= 1;
    }

    // ---- epilogue ----
    const int g4 = lane >> 2;          // 0..7
    const int t4 = lane & 3;           // 0..3
#pragma unroll
    for (int mt = 0; mt < 2; mt++) {
#pragma unroll
        for (int rh = 0; rh < 2; rh++) {
            const int row = wm * 32 + mt * 16 + g4 + rh * 8;
#pragma unroll
            for (int nt = 0; nt < 4; nt++) {
                const int col = n0 + wn * 32 + nt * 8 + t4 * 2;
                float v0 = acc[mt][nt][rh * 2 + 0];
                float v1 = acc[mt][nt][rh * 2 + 1];
                if (emode == 0) {
                    const float2 a1 = *reinterpret_cast<const float2*>(cs1 + (size_t)row * DN + col);
                    const float2 a2 = *reinterpret_cast<const float2*>(cs2 + (size_t)row * DN + col);
                    const float2 a3 = *reinterpret_cast<const float2*>(cs3 + (size_t)row * DN + col);
                    const float2 w0 = *reinterpret_cast<const float2*>(cw + 0 * DN + col);
                    const float2 w1 = *reinterpret_cast<const float2*>(cw + 1 * DN + col);
                    const float2 w2 = *reinterpret_cast<const float2*>(cw + 2 * DN + col);
                    const float2 w3 = *reinterpret_cast<const float2*>(cw + 3 * DN + col);
                    const float2 bv = *reinterpret_cast<const float2*>(cb + col);
                    float s0 = bv.x + w0.x * a1.x + w1.x * a2.x + w2.x * a3.x + w3.x * v0;
                    float s1 = bv.y + w0.y * a1.y + w1.y * a2.y + w2.y * a3.y + w3.y * v1;
                    float2 o;
                    o.x = s0 / (1.0f + expf(-s0));
                    o.y = s1 / (1.0f + expf(-s1));
                    *reinterpret_cast<float2*>(C + (size_t)row * ldC + col) = o;
                } else if (emode == 1) {
                    float2 o; o.x = v0; o.y = v1;
                    *reinterpret_cast<float2*>(C + (size_t)row * ldC + col) = o;
                } else {
                    atomicAdd(C + (size_t)row * ldC + col, v0);
                    atomicAdd(C + (size_t)row * ldC + col + 1, v1);
                }
            }
        }
    }
}

// ---------------- fp32 split-K SGEMM (tiny proj GEMM only) ----
__global__ __launch_bounds__(256, 3)
void sgemm_atomic(const float* __restrict__ A, const float* __restrict__ B,
                  float* __restrict__ C, int K, int N, int lda, int kslice) {
    __shared__ float As[16][128];
    __shared__ float Bs[16][64];

    const int n0 = blockIdx.x * 64;
    int k0 = blockIdx.y * kslice;
    int kend = k0 + kslice;
    if (kend > K) kend = K;

    const int t  = threadIdx.x;
    const int ty = t >> 4;
    const int tx = t & 15;
    const int an   = t >> 1;
    const int aseg = t & 1;
    const int bk = t >> 4;
    const int bj = (t & 15) << 2;

    unsigned long long acc[4][4];
#pragma unroll
    for (int i = 0; i < 4; i++)
#pragma unroll
        for (int j = 0; j < 4; j++) acc[i][j] = 0ull;

    for (; k0 < kend; k0 += 16) {
        const float4 av0 = *reinterpret_cast<const float4*>(A + an * lda + k0 + aseg * 8);
        const float4 av1 = *reinterpret_cast<const float4*>(A + an * lda + k0 + aseg * 8 + 4);
        const float4 bv  = *reinterpret_cast<const float4*>(B + (k0 + bk) * N + n0 + bj);

        As[aseg * 8 + 0][an] = av0.x;
        As[aseg * 8 + 1][an] = av0.y;
        As[aseg * 8 + 2][an] = av0.z;
        As[aseg * 8 + 3][an] = av0.w;
        As[aseg * 8 + 4][an] = av1.x;
        As[aseg * 8 + 5][an] = av1.y;
        As[aseg * 8 + 6][an] = av1.z;
        As[aseg * 8 + 7][an] = av1.w;
        *reinterpret_cast<float4*>(&Bs[bk][bj]) = bv;
        __syncthreads();

#pragma unroll
        for (int kk = 0; kk < 16; kk++) {
            unsigned long long a[4];
#pragma unroll
            for (int i = 0; i < 4; i++)
                a[i] = *reinterpret_cast<const unsigned long long*>(&As[kk][ty * 8 + 2 * i]);
            const float4 b4 = *reinterpret_cast<const float4*>(&Bs[kk][tx * 4]);
            unsigned long long b[4];
            b[0] = pack2(b4.x, b4.x);
            b[1] = pack2(b4.y, b4.y);
            b[2] = pack2(b4.z, b4.z);
            b[3] = pack2(b4.w, b4.w);
#pragma unroll
            for (int i = 0; i < 4; i++)
#pragma unroll
                for (int j = 0; j < 4; j++) fma2(acc[i][j], a[i], b[j]);
        }
        __syncthreads();
    }

#pragma unroll
    for (int i = 0; i < 4; i++) {
        const int r0 = ty * 8 + 2 * i;
#pragma unroll
        for (int j = 0; j < 4; j++) {
            float lo, hi;
            unpack2(acc[i][j], lo, hi);
            const int c = n0 + tx * 4 + j;
            atomicAdd(&C[r0 * N + c], lo);
            atomicAdd(&C[(r0 + 1) * N + c], hi);
        }
    }
}

// ---------------- fused dt-GEMM + softplus + SSM scan + gate ----------------
__global__ __launch_bounds__(256)
void ssm_kernel(const float* __restrict__ dt_w,    // [160, 5120]
                const float* __restrict__ dt_b,    // [5120]
                const float* __restrict__ A_log,   // [5120, 16]
                const float* __restrict__ state,   // [128, 5120, 16]
                const float* __restrict__ D_param) // [5120]
{
    const int d  = blockIdx.x * 256 + threadIdx.x;
    const int nb = blockIdx.y * 8;

    __shared__ float pj[8][PJ];
    for (int i = threadIdx.x; i < 8 * PJ; i += 256)
        pj[i / PJ][i % PJ] = g_proj[(nb + i / PJ) * PJ + (i % PJ)];
    __syncthreads();

    float dtp[8];
    const float bias = dt_b[d];
#pragma unroll
    for (int i = 0; i < 8; i++) dtp[i] = bias;
#pragma unroll 4
    for (int r = 0; r < RR; r++) {
        const float w = dt_w[r * DN + d];
#pragma unroll
        for (int i = 0; i < 8; i++) dtp[i] += pj[i][r] * w;
    }

    float Aa[SS];
#pragma unroll
    for (int s = 0; s < SS; s++) Aa[s] = -expf(A_log[d * SS + s]);
    const float Dv = D_param[d];

#pragma unroll
    for (int i = 0; i < 8; i++) {
        const int n = nb + i;
        const float x  = dtp[i];
        const float dt = (x > 20.0f) ? x : log1pf(expf(x));
        const float uv = g_u[n * DN + d];
        const float rv = g_res[n * DN + d];
        const float4* st = reinterpret_cast<const float4*>(state + ((long)n * DN + d) * SS);
        float y = 0.0f;
#pragma unroll
        for (int q = 0; q < 4; q++) {
            const float4 sv = st[q];
            {   const int s = q * 4 + 0;
                const float h = expf(dt * Aa[s]) * sv.x + dt * pj[i][RR + s] * uv;
                y += h * pj[i][RR + SS + s]; }
            {   const int s = q * 4 + 1;
                const float h = expf(dt * Aa[s]) * sv.y + dt * pj[i][RR + s] * uv;
                y += h * pj[i][RR + SS + s]; }
            {   const int s = q * 4 + 2;
                const float h = expf(dt * Aa[s]) * sv.z + dt * pj[i][RR + s] * uv;
                y += h * pj[i][RR + SS + s]; }
            {   const int s = q * 4 + 3;
                const float h = expf(dt * Aa[s]) * sv.w + dt * pj[i][RR + s] * uv;
                y += h * pj[i][RR + SS + s]; }
        }
        y += Dv * uv;
        g_g[n * DN + d] = y * rv;
    }
}

// ---------------- launcher ----------------
extern "C" void kernel_launch(void* const* d_in, const int* in_sizes, int n_in,
                              void* d_out, int out_size) {
    const float* x        = (const float*)d_in[0];
    const float* cs1      = (const float*)d_in[2];
    const float* cs2      = (const float*)d_in[3];
    const float* cs3      = (const float*)d_in[4];
    const float* state    = (const float*)d_in[5];
    const float* ssm_proj = (const float*)d_in[6];
    const float* mlp_proj = (const float*)d_in[7];
    const float* down_prj = (const float*)d_in[8];
    const float* conv_w   = (const float*)d_in[9];
    const float* conv_b   = (const float*)d_in[10];
    const float* x_proj_w = (const float*)d_in[11];
    const float* dt_w     = (const float*)d_in[12];
    const float* dt_b     = (const float*)d_in[13];
    const float* A_log    = (const float*)d_in[14];
    const float* Dp       = (const float*)d_in[15];
    float* out = (float*)d_out;

    void *p_res, *p_u, *p_proj, *p_xhi, *p_xlo, *p_ghi, *p_glo, *p_g;
    cudaGetSymbolAddress(&p_res,  g_res);
    cudaGetSymbolAddress(&p_u,    g_u);
    cudaGetSymbolAddress(&p_proj, g_proj);
    cudaGetSymbolAddress(&p_g,    g_g);
    cudaGetSymbolAddress(&p_xhi,  g_xhi);
    cudaGetSymbolAddress(&p_xlo,  g_xlo);
    cudaGetSymbolAddress(&p_ghi,  g_ghi);
    cudaGetSymbolAddress(&p_glo,  g_glo);

    cudaFuncSetAttribute(gemm_hmma, cudaFuncAttributeMaxDynamicSharedMemorySize,
                         SMEM_DYN);

    // 0) zero output + proj accumulator; split x -> bf16 hi/lo
    zero_k<<<(NB * DD + 255) / 256, 256>>>(out);
    convert_split<<<(NB * DD + 255) / 256, 256>>>(
        x, (__nv_bfloat16*)p_xhi, (__nv_bfloat16*)p_xlo, NB * DD);

    // 1+2+3) u = silu(conv(x@ssm_proj)) and res = x@mlp_proj (fused epilogues)
    gemm_hmma<<<dim3(160, 1), 256, SMEM_DYN>>>(
        (const __nv_bfloat16*)p_xhi, (const __nv_bfloat16*)p_xlo, DD, DD / CH_K,
        ssm_proj, mlp_proj, DN, (float*)p_u, (float*)p_res, 0,
        cs1, cs2, cs3, conv_w, conv_b);

    // 4) proj = u @ x_proj_w  (fp32, K=5120, N=192, split-K 40)
    sgemm_atomic<<<dim3(PJ / 64, 40), 256>>>((const float*)p_u, x_proj_w,
                                             (float*)p_proj, DN, PJ, DN, 128);

    // 5) dt GEMM + softplus + SSM scan + D*u + gate -> g_g
    ssm_kernel<<<dim3(DN / 256, NB / 8), 256>>>(dt_w, dt_b, A_log, state, Dp);

    // 6) split g -> bf16 hi/lo; out = g @ down_proj (split-K 4, atomic)
    convert_split<<<(NB * DN + 255) / 256, 256>>>(
        (const float*)p_g, (__nv_bfloat16*)p_ghi, (__nv_bfloat16*)p_glo, NB * DN);
    gemm_hmma<<<dim3(DD / 64, 4), 256, SMEM_DYN>>>(
        (const __nv_bfloat16*)p_ghi, (const __nv_bfloat16*)p_glo, DN,
        (DN / 4) / CH_K, down_prj, nullptr, DD, out, nullptr, 2,
        nullptr, nullptr, nullptr, nullptr, nullptr);
}